// round 5
// baseline (speedup 1.0000x reference)
#include <cuda_runtime.h>
#include <cuda_bf16.h>
#include <math_constants.h>

// Problem constants
#define NB    2048      // queries
#define NP    100000    // data points
#define DD    64        // dim
#define KK    20        // top-k
#define ZLD   66        // z row stride (D+2)

// KNN pass-1 tiling
#define NCH   128       // point chunks
#define CHUNK 784       // points per chunk
#define KEEP  7         // candidates kept per (query, chunk)
#define TS    64        // shared tile points
#define P1T   128       // threads per pass-1 block
#define QPT   2         // queries per thread
#define PADP  100416    // padded point count (covers 127*784+832)
#define CAND  (NCH * KEEP)   // 896

// Scratch (device globals; no allocation allowed)
__device__ float              g_pn2[PADP];
__device__ unsigned long long g_cand[(size_t)NB * CAND];   // (d2bits<<32)|gidx

// packed f32x2 helpers
#define FMA2(acc, a, b) asm("fma.rn.f32x2 %0, %1, %2, %0;" : "+l"(acc) : "l"(a), "l"(b))
#define ADD2(d, a, b)   asm("add.rn.f32x2 %0, %1, %2;" : "=l"(d) : "l"(a), "l"(b))
#define PACK2(d, x, y)  asm("mov.b64 %0, {%1, %2};" : "=l"(d) : "f"(x), "f"(y))
#define UNPK2(lo, hi, v) asm("mov.b64 {%0, %1}, %2;" : "=f"(lo), "=f"(hi) : "l"(v))

// ---------------------------------------------------------------------------
// Kernel 0: per-point squared norms (+INF for padding)
// ---------------------------------------------------------------------------
__global__ void pn2_kernel(const float* __restrict__ data) {
    int i = blockIdx.x * 256 + threadIdx.x;
    if (i >= PADP) return;
    if (i >= NP) { g_pn2[i] = CUDART_INF_F; return; }
    const float4* r = (const float4*)(data + (size_t)i * DD);
    float s = 0.f;
#pragma unroll
    for (int k = 0; k < 16; k++) {
        float4 v = r[k];
        s = fmaf(v.x, v.x, s);
        s = fmaf(v.y, v.y, s);
        s = fmaf(v.z, v.z, s);
        s = fmaf(v.w, v.w, s);
    }
    g_pn2[i] = s;
}

// ---------------------------------------------------------------------------
// Kernel 1: MLP  x_dot = relu([x,t]@W1+b1)@W2+b2  -> out cols [0,64)
// ---------------------------------------------------------------------------
__global__ __launch_bounds__(256) void mlp_kernel(
    const float* __restrict__ z, const float* __restrict__ t,
    const float* __restrict__ W1, const float* __restrict__ b1,
    const float* __restrict__ W2, const float* __restrict__ b2,
    float* __restrict__ out)
{
    __shared__ float sin_[8][65];
    __shared__ float sh[8][256];
    int qb = blockIdx.x * 8;
    int tid = threadIdx.x;

    for (int i = tid; i < 8 * 64; i += 256)
        sin_[i >> 6][i & 63] = z[(size_t)(qb + (i >> 6)) * ZLD + (i & 63)];
    if (tid < 8) sin_[tid][64] = t[0];
    __syncthreads();

    float acc[8];
#pragma unroll
    for (int i = 0; i < 8; i++) acc[i] = b1[tid];
    for (int d = 0; d < 65; d++) {
        float w = W1[d * 256 + tid];
#pragma unroll
        for (int i = 0; i < 8; i++) acc[i] = fmaf(sin_[i][d], w, acc[i]);
    }
#pragma unroll
    for (int i = 0; i < 8; i++) sh[i][tid] = fmaxf(acc[i], 0.f);
    __syncthreads();

#pragma unroll
    for (int rep = 0; rep < 2; rep++) {
        int qi = rep * 4 + (tid >> 6);
        int d  = tid & 63;
        float o = b2[d];
        for (int j = 0; j < 256; j++) o = fmaf(sh[qi][j], W2[j * 64 + d], o);
        out[(size_t)(qb + qi) * ZLD + d] = o;
    }
}

// ---------------------------------------------------------------------------
// Kernel 2: KNN pass 1 — dim-pair packed f32x2, 2 queries/thread.
// Point tile is point-major in shared; each broadcast LDS.64 of (p_d,p_{d+1})
// feeds 2 FFMA2 (one per register-resident query). Emits per (query,chunk)
// top-KEEP as (d2bits<<32)|gidx.
// ---------------------------------------------------------------------------
__global__ __launch_bounds__(P1T) void knn_pass1(
    const float* __restrict__ z, const float* __restrict__ data)
{
    __shared__ __align__(16) float sP[TS * DD];   // point-major [j][d]
    __shared__ float sN[TS];

    int tid   = threadIdx.x;
    int gq    = blockIdx.x * P1T + tid;     // query-pair id
    int q0    = gq * 2;
    int chunk = blockIdx.y;
    int cs    = chunk * CHUNK;

    // two queries, dim-pair packed: qp[i] = (q_{2i}, q_{2i+1})
    unsigned long long qa[32], qb[32];
    float qn2a = 0.f, qn2b = 0.f;
    {
        const float2* z0 = (const float2*)(z + (size_t)q0 * ZLD);
        const float2* z1 = (const float2*)(z + (size_t)(q0 + 1) * ZLD);
#pragma unroll
        for (int i = 0; i < 32; i++) {
            float2 v0 = z0[i];
            float2 v1 = z1[i];
            qn2a = fmaf(v0.x, v0.x, qn2a); qn2a = fmaf(v0.y, v0.y, qn2a);
            qn2b = fmaf(v1.x, v1.x, qn2b); qn2b = fmaf(v1.y, v1.y, qn2b);
            PACK2(qa[i], v0.x, v0.y);
            PACK2(qb[i], v1.x, v1.y);
        }
    }

    unsigned ka[KEEP], kb_[KEEP];
    float    da[KEEP], db[KEEP];
#pragma unroll
    for (int i = 0; i < KEEP; i++) {
        ka[i] = 0xFFFFFFFFu; kb_[i] = 0xFFFFFFFFu;
        da[i] = CUDART_INF_F; db[i] = CUDART_INF_F;
    }

    // 13 tiles of 64 cover [cs, cs+832); pads have pn2=+INF (self-rejecting)
    for (int tt = 0; tt < 13; tt++) {
        int t0 = cs + tt * TS;
        __syncthreads();
        // load tile point-major (coalesced float4), zero rows past NP
        for (int i = tid; i < TS * 16; i += P1T) {
            int row = i >> 4, g = i & 15;
            int p = t0 + row;
            float4 v = make_float4(0.f, 0.f, 0.f, 0.f);
            if (p < NP) v = ((const float4*)(data + (size_t)p * DD))[g];
            ((float4*)sP)[i] = v;
        }
        if (tid < TS) sN[tid] = g_pn2[t0 + tid];
        __syncthreads();

        int lbase = t0 - cs;
        for (int j = 0; j < TS; j++) {
            const unsigned long long* pd =
                (const unsigned long long*)(sP + (j << 6));
            unsigned long long a0 = 0ULL, a1 = 0ULL, b0 = 0ULL, b1 = 0ULL;
#pragma unroll
            for (int i = 0; i < 32; i += 2) {
                unsigned long long v0 = pd[i];
                unsigned long long v1 = pd[i + 1];
                FMA2(a0, qa[i],     v0);
                FMA2(b0, qb[i],     v0);
                FMA2(a1, qa[i + 1], v1);
                FMA2(b1, qb[i + 1], v1);
            }
            float snj = sN[j];
            unsigned long long as, bs;
            ADD2(as, a0, a1);
            ADD2(bs, b0, b1);
            float alo, ahi, blo, bhi;
            UNPK2(alo, ahi, as);
            UNPK2(blo, bhi, bs);
            float dotA = alo + ahi;
            float dotB = blo + bhi;
            float d2A = fmaxf(fmaf(-2.f, dotA, qn2a + snj), 0.f);
            float d2B = fmaxf(fmaf(-2.f, dotB, qn2b + snj), 0.f);
            unsigned lidx = (unsigned)(lbase + j);
            unsigned keyA = (__float_as_uint(d2A) & 0xFFFFF800u) | lidx;
            unsigned keyB = (__float_as_uint(d2B) & 0xFFFFF800u) | lidx;
            if (keyA < ka[KEEP - 1]) {
                unsigned ik = keyA; float id = d2A;
#pragma unroll
                for (int i = 0; i < KEEP; i++) {
                    if (ik < ka[i]) {
                        unsigned tk = ka[i]; ka[i] = ik; ik = tk;
                        float    td = da[i]; da[i] = id; id = td;
                    }
                }
            }
            if (keyB < kb_[KEEP - 1]) {
                unsigned ik = keyB; float id = d2B;
#pragma unroll
                for (int i = 0; i < KEEP; i++) {
                    if (ik < kb_[i]) {
                        unsigned tk = kb_[i]; kb_[i] = ik; ik = tk;
                        float    td = db[i]; db[i] = id; id = td;
                    }
                }
            }
        }
    }

    unsigned long long* oc0 = g_cand + (size_t)q0 * CAND + chunk * KEEP;
    unsigned long long* oc1 = oc0 + CAND;
#pragma unroll
    for (int i = 0; i < KEEP; i++) {
        oc0[i] = ((unsigned long long)__float_as_uint(da[i]) << 32) |
                 ((unsigned)cs + (ka[i] & 0x7FFu));
        oc1[i] = ((unsigned long long)__float_as_uint(db[i]) << 32) |
                 ((unsigned)cs + (kb_[i] & 0x7FFu));
    }
}

// ---------------------------------------------------------------------------
// Kernel 3: pass 2 — barrier-light exact top-20 over 896 candidates,
// weights, u_t, cos_sim + L2 -> out cols 64,65.
// ---------------------------------------------------------------------------
__global__ __launch_bounds__(256) void knn_pass2(
    const float* __restrict__ vel, float* __restrict__ out)
{
    __shared__ unsigned long long sA[7 * KK];
    __shared__ float sdist[KK];
    __shared__ float swgt[KK];
    __shared__ int   sidx[KK];
    __shared__ float s_wsum;
    __shared__ float pr_ux[DD], pr_uu[DD], pr_xx[DD], pr_l2[DD];

    int q   = blockIdx.x;
    int tid = threadIdx.x;
    int wid = tid >> 5;
    int lane = tid & 31;
    const unsigned long long UMAX = ~0ULL;

    unsigned long long kr[4];
    if (wid < 7) {
        const unsigned long long* src = g_cand + (size_t)q * CAND + wid * 128 + lane;
#pragma unroll
        for (int i = 0; i < 4; i++) kr[i] = src[32 * i];
    } else {
#pragma unroll
        for (int i = 0; i < 4; i++) kr[i] = UMAX;
    }

    if (wid < 7) {
        for (int r = 0; r < KK; r++) {
            unsigned long long m0 = kr[0] < kr[1] ? kr[0] : kr[1];
            unsigned long long m1 = kr[2] < kr[3] ? kr[2] : kr[3];
            unsigned long long m = m0 < m1 ? m0 : m1;
#pragma unroll
            for (int o = 16; o > 0; o >>= 1) {
                unsigned long long v = __shfl_xor_sync(0xffffffffu, m, o);
                if (v < m) m = v;
            }
#pragma unroll
            for (int i = 0; i < 4; i++) if (kr[i] == m) kr[i] = UMAX;
            if (lane == 0) sA[wid * KK + r] = m;
        }
    }
    __syncthreads();

    if (wid == 0) {
        unsigned long long kb[5];
#pragma unroll
        for (int i = 0; i < 5; i++) {
            int j = lane + 32 * i;
            kb[i] = (j < 7 * KK) ? sA[j] : UMAX;
        }
        for (int r = 0; r < KK; r++) {
            unsigned long long m = kb[0];
#pragma unroll
            for (int i = 1; i < 5; i++) if (kb[i] < m) m = kb[i];
#pragma unroll
            for (int o = 16; o > 0; o >>= 1) {
                unsigned long long v = __shfl_xor_sync(0xffffffffu, m, o);
                if (v < m) m = v;
            }
#pragma unroll
            for (int i = 0; i < 5; i++) if (kb[i] == m) kb[i] = UMAX;
            if (lane == 0) {
                float d2 = __uint_as_float((unsigned)(m >> 32));
                sdist[r] = sqrtf(fmaxf(d2, 1e-30f));
                sidx[r]  = (int)(m & 0xFFFFFFFFu);
            }
        }
    }
    __syncthreads();

    if (tid < KK) {
        float h = fmaxf(sdist[KK - 1], 1e-12f);
        float dd = sdist[tid];
        swgt[tid] = expf(-(dd * dd) / (2.f * h * h));
    }
    __syncthreads();
    if (tid == 0) {
        float s = 0.f;
        for (int i = 0; i < KK; i++) s += swgt[i];
        s_wsum = s + 1e-12f;
    }
    __syncthreads();

    if (tid < DD) {
        float u = 0.f;
#pragma unroll
        for (int i = 0; i < KK; i++)
            u = fmaf(swgt[i], vel[(size_t)sidx[i] * DD + tid], u);
        u *= (1.f / s_wsum);
        float xd = out[(size_t)q * ZLD + tid];
        pr_ux[tid] = u * xd;
        pr_uu[tid] = u * u;
        pr_xx[tid] = xd * xd;
        float dfe = u - xd;
        pr_l2[tid] = dfe * dfe;
    }
    __syncthreads();
    if (tid == 0) {
        float ux = 0.f, uu = 0.f, xx = 0.f, l2 = 0.f;
        for (int d = 0; d < DD; d++) {
            ux += pr_ux[d]; uu += pr_uu[d]; xx += pr_xx[d]; l2 += pr_l2[d];
        }
        float nu = fmaxf(sqrtf(uu), 1e-8f);
        float nx = fmaxf(sqrtf(xx), 1e-8f);
        out[(size_t)q * ZLD + 64] = 1.f - ux / (nu * nx);
        out[(size_t)q * ZLD + 65] = l2;
    }
}

// ---------------------------------------------------------------------------
extern "C" void kernel_launch(void* const* d_in, const int* in_sizes, int n_in,
                              void* d_out, int out_size)
{
    const float* t    = (const float*)d_in[0];
    const float* z    = (const float*)d_in[1];
    const float* data = (const float*)d_in[2];
    const float* vel  = (const float*)d_in[3];
    const float* W1   = (const float*)d_in[4];
    const float* b1   = (const float*)d_in[5];
    const float* W2   = (const float*)d_in[6];
    const float* b2   = (const float*)d_in[7];
    float* out = (float*)d_out;

    pn2_kernel<<<(PADP + 255) / 256, 256>>>(data);
    mlp_kernel<<<NB / 8, 256>>>(z, t, W1, b1, W2, b2, out);
    knn_pass1<<<dim3(NB / (P1T * QPT), NCH), P1T>>>(z, data);
    knn_pass2<<<NB, 256>>>(vel, out);
}

// round 7
// speedup vs baseline: 1.6533x; 1.6533x over previous
#include <cuda_runtime.h>
#include <cuda_bf16.h>
#include <math_constants.h>

// Problem constants
#define NB    2048      // queries
#define NP    100000    // data points
#define DD    64        // dim
#define KK    20        // top-k
#define ZLD   66        // z row stride (D+2)

// KNN pass-1 tiling
#define NCH   128       // point chunks
#define CHUNK 784       // points per chunk
#define KEEP  7         // candidates kept per (query, chunk)
#define TS    64        // shared tile points
#define P1T   128       // threads per pass-1 block
#define QPT   2         // queries per thread
#define PADP  100416    // padded point count (covers 127*784+832)
#define CAND  (NCH * KEEP)   // 896

// Scratch (device globals; no allocation allowed)
__device__ float              g_pn2[PADP];
__device__ unsigned long long g_cand[(size_t)NB * CAND];   // (d2bits<<32)|gidx

// packed f32x2 helpers
#define FMA2(acc, a, b) asm("fma.rn.f32x2 %0, %1, %2, %0;" : "+l"(acc) : "l"(a), "l"(b))
#define ADD2(d, a, b)   asm("add.rn.f32x2 %0, %1, %2;" : "=l"(d) : "l"(a), "l"(b))
#define PACK2(d, x, y)  asm("mov.b64 %0, {%1, %2};" : "=l"(d) : "f"(x), "f"(y))
#define UNPK2(lo, hi, v) asm("mov.b64 {%0, %1}, %2;" : "=f"(lo), "=f"(hi) : "l"(v))

// ---------------------------------------------------------------------------
// Kernel 0: per-point squared norms (+INF for padding)
// ---------------------------------------------------------------------------
__global__ void pn2_kernel(const float* __restrict__ data) {
    int i = blockIdx.x * 256 + threadIdx.x;
    if (i >= PADP) return;
    if (i >= NP) { g_pn2[i] = CUDART_INF_F; return; }
    const float4* r = (const float4*)(data + (size_t)i * DD);
    float s = 0.f;
#pragma unroll
    for (int k = 0; k < 16; k++) {
        float4 v = r[k];
        s = fmaf(v.x, v.x, s);
        s = fmaf(v.y, v.y, s);
        s = fmaf(v.z, v.z, s);
        s = fmaf(v.w, v.w, s);
    }
    g_pn2[i] = s;
}

// ---------------------------------------------------------------------------
// Kernel 1: MLP  x_dot = relu([x,t]@W1+b1)@W2+b2  -> out cols [0,64)
// ---------------------------------------------------------------------------
__global__ __launch_bounds__(256) void mlp_kernel(
    const float* __restrict__ z, const float* __restrict__ t,
    const float* __restrict__ W1, const float* __restrict__ b1,
    const float* __restrict__ W2, const float* __restrict__ b2,
    float* __restrict__ out)
{
    __shared__ float sin_[8][65];
    __shared__ float sh[8][256];
    int qb = blockIdx.x * 8;
    int tid = threadIdx.x;

    for (int i = tid; i < 8 * 64; i += 256)
        sin_[i >> 6][i & 63] = z[(size_t)(qb + (i >> 6)) * ZLD + (i & 63)];
    if (tid < 8) sin_[tid][64] = t[0];
    __syncthreads();

    float acc[8];
#pragma unroll
    for (int i = 0; i < 8; i++) acc[i] = b1[tid];
    for (int d = 0; d < 65; d++) {
        float w = W1[d * 256 + tid];
#pragma unroll
        for (int i = 0; i < 8; i++) acc[i] = fmaf(sin_[i][d], w, acc[i]);
    }
#pragma unroll
    for (int i = 0; i < 8; i++) sh[i][tid] = fmaxf(acc[i], 0.f);
    __syncthreads();

#pragma unroll
    for (int rep = 0; rep < 2; rep++) {
        int qi = rep * 4 + (tid >> 6);
        int d  = tid & 63;
        float o = b2[d];
        for (int j = 0; j < 256; j++) o = fmaf(sh[qi][j], W2[j * 64 + d], o);
        out[(size_t)(qb + qi) * ZLD + d] = o;
    }
}

// ---------------------------------------------------------------------------
// Kernel 2: KNN pass 1 — dim-pair packed f32x2, 2 queries/thread,
// LDS.128 point loads (4 dims -> 4 FFMA2). __launch_bounds__(128,1) unlocks
// the 255-reg budget so both query vectors stay register-resident (no spill).
// Emits per (query,chunk) top-KEEP as (d2bits<<32)|gidx.
// ---------------------------------------------------------------------------
__global__ void __launch_bounds__(P1T, 1) knn_pass1(
    const float* __restrict__ z, const float* __restrict__ data)
{
    __shared__ __align__(16) float sP[TS * DD];   // point-major [j][d]
    __shared__ float sN[TS];

    int tid   = threadIdx.x;
    int q0    = (blockIdx.x * P1T + tid) * QPT;
    int chunk = blockIdx.y;
    int cs    = chunk * CHUNK;

    // two queries, dim-pair packed: qa[i] = (q_{2i}, q_{2i+1})
    unsigned long long qa[32], qb[32];
    float qn2a = 0.f, qn2b = 0.f;
    {
        const float2* z0 = (const float2*)(z + (size_t)q0 * ZLD);
        const float2* z1 = (const float2*)(z + (size_t)(q0 + 1) * ZLD);
#pragma unroll
        for (int i = 0; i < 32; i++) {
            float2 v0 = z0[i];
            float2 v1 = z1[i];
            qn2a = fmaf(v0.x, v0.x, qn2a); qn2a = fmaf(v0.y, v0.y, qn2a);
            qn2b = fmaf(v1.x, v1.x, qn2b); qn2b = fmaf(v1.y, v1.y, qn2b);
            PACK2(qa[i], v0.x, v0.y);
            PACK2(qb[i], v1.x, v1.y);
        }
    }

    unsigned ka[KEEP], kb_[KEEP];
    float    da[KEEP], db[KEEP];
#pragma unroll
    for (int i = 0; i < KEEP; i++) {
        ka[i] = 0xFFFFFFFFu; kb_[i] = 0xFFFFFFFFu;
        da[i] = CUDART_INF_F; db[i] = CUDART_INF_F;
    }

    // 13 tiles of 64 cover [cs, cs+832); pads have pn2=+INF (self-rejecting)
    for (int tt = 0; tt < 13; tt++) {
        int t0 = cs + tt * TS;
        __syncthreads();
        // load tile point-major (coalesced float4), zero rows past NP
        for (int i = tid; i < TS * 16; i += P1T) {
            int row = i >> 4, g = i & 15;
            int p = t0 + row;
            float4 v = make_float4(0.f, 0.f, 0.f, 0.f);
            if (p < NP) v = ((const float4*)(data + (size_t)p * DD))[g];
            ((float4*)sP)[i] = v;
        }
        if (tid < TS) sN[tid] = g_pn2[t0 + tid];
        __syncthreads();

        int lbase = t0 - cs;
        for (int j = 0; j < TS; j++) {
            const ulonglong2* pd = (const ulonglong2*)(sP + (j << 6));
            unsigned long long a0 = 0ULL, a1 = 0ULL, b0 = 0ULL, b1 = 0ULL;
#pragma unroll
            for (int i = 0; i < 16; i++) {
                ulonglong2 v = pd[i];          // dims 4i..4i+3 of point j
                FMA2(a0, qa[2 * i],     v.x);
                FMA2(b0, qb[2 * i],     v.x);
                FMA2(a1, qa[2 * i + 1], v.y);
                FMA2(b1, qb[2 * i + 1], v.y);
            }
            float snj = sN[j];
            unsigned long long as, bs;
            ADD2(as, a0, a1);
            ADD2(bs, b0, b1);
            float alo, ahi, blo, bhi;
            UNPK2(alo, ahi, as);
            UNPK2(blo, bhi, bs);
            float dotA = alo + ahi;
            float dotB = blo + bhi;
            float d2A = fmaxf(fmaf(-2.f, dotA, qn2a + snj), 0.f);
            float d2B = fmaxf(fmaf(-2.f, dotB, qn2b + snj), 0.f);
            unsigned lidx = (unsigned)(lbase + j);
            unsigned keyA = (__float_as_uint(d2A) & 0xFFFFF800u) | lidx;
            unsigned keyB = (__float_as_uint(d2B) & 0xFFFFF800u) | lidx;
            if (keyA < ka[KEEP - 1]) {
                unsigned ik = keyA; float id = d2A;
#pragma unroll
                for (int i = 0; i < KEEP; i++) {
                    if (ik < ka[i]) {
                        unsigned tk = ka[i]; ka[i] = ik; ik = tk;
                        float    td = da[i]; da[i] = id; id = td;
                    }
                }
            }
            if (keyB < kb_[KEEP - 1]) {
                unsigned ik = keyB; float id = d2B;
#pragma unroll
                for (int i = 0; i < KEEP; i++) {
                    if (ik < kb_[i]) {
                        unsigned tk = kb_[i]; kb_[i] = ik; ik = tk;
                        float    td = db[i]; db[i] = id; id = td;
                    }
                }
            }
        }
    }

    unsigned long long* oc0 = g_cand + (size_t)q0 * CAND + chunk * KEEP;
    unsigned long long* oc1 = oc0 + CAND;
#pragma unroll
    for (int i = 0; i < KEEP; i++) {
        oc0[i] = ((unsigned long long)__float_as_uint(da[i]) << 32) |
                 ((unsigned)cs + (ka[i] & 0x7FFu));
        oc1[i] = ((unsigned long long)__float_as_uint(db[i]) << 32) |
                 ((unsigned)cs + (kb_[i] & 0x7FFu));
    }
}

// ---------------------------------------------------------------------------
// Kernel 3: pass 2 — barrier-light exact top-20 over 896 candidates,
// weights, u_t, cos_sim + L2 -> out cols 64,65.
// ---------------------------------------------------------------------------
__global__ __launch_bounds__(256) void knn_pass2(
    const float* __restrict__ vel, float* __restrict__ out)
{
    __shared__ unsigned long long sA[7 * KK];
    __shared__ float sdist[KK];
    __shared__ float swgt[KK];
    __shared__ int   sidx[KK];
    __shared__ float s_wsum;
    __shared__ float pr_ux[DD], pr_uu[DD], pr_xx[DD], pr_l2[DD];

    int q   = blockIdx.x;
    int tid = threadIdx.x;
    int wid = tid >> 5;
    int lane = tid & 31;
    const unsigned long long UMAX = ~0ULL;

    unsigned long long kr[4];
    if (wid < 7) {
        const unsigned long long* src = g_cand + (size_t)q * CAND + wid * 128 + lane;
#pragma unroll
        for (int i = 0; i < 4; i++) kr[i] = src[32 * i];
    } else {
#pragma unroll
        for (int i = 0; i < 4; i++) kr[i] = UMAX;
    }

    if (wid < 7) {
        for (int r = 0; r < KK; r++) {
            unsigned long long m0 = kr[0] < kr[1] ? kr[0] : kr[1];
            unsigned long long m1 = kr[2] < kr[3] ? kr[2] : kr[3];
            unsigned long long m = m0 < m1 ? m0 : m1;
#pragma unroll
            for (int o = 16; o > 0; o >>= 1) {
                unsigned long long v = __shfl_xor_sync(0xffffffffu, m, o);
                if (v < m) m = v;
            }
#pragma unroll
            for (int i = 0; i < 4; i++) if (kr[i] == m) kr[i] = UMAX;
            if (lane == 0) sA[wid * KK + r] = m;
        }
    }
    __syncthreads();

    if (wid == 0) {
        unsigned long long kb[5];
#pragma unroll
        for (int i = 0; i < 5; i++) {
            int j = lane + 32 * i;
            kb[i] = (j < 7 * KK) ? sA[j] : UMAX;
        }
        for (int r = 0; r < KK; r++) {
            unsigned long long m = kb[0];
#pragma unroll
            for (int i = 1; i < 5; i++) if (kb[i] < m) m = kb[i];
#pragma unroll
            for (int o = 16; o > 0; o >>= 1) {
                unsigned long long v = __shfl_xor_sync(0xffffffffu, m, o);
                if (v < m) m = v;
            }
#pragma unroll
            for (int i = 0; i < 5; i++) if (kb[i] == m) kb[i] = UMAX;
            if (lane == 0) {
                float d2 = __uint_as_float((unsigned)(m >> 32));
                sdist[r] = sqrtf(fmaxf(d2, 1e-30f));
                sidx[r]  = (int)(m & 0xFFFFFFFFu);
            }
        }
    }
    __syncthreads();

    if (tid < KK) {
        float h = fmaxf(sdist[KK - 1], 1e-12f);
        float dd = sdist[tid];
        swgt[tid] = expf(-(dd * dd) / (2.f * h * h));
    }
    __syncthreads();
    if (tid == 0) {
        float s = 0.f;
        for (int i = 0; i < KK; i++) s += swgt[i];
        s_wsum = s + 1e-12f;
    }
    __syncthreads();

    if (tid < DD) {
        float u = 0.f;
#pragma unroll
        for (int i = 0; i < KK; i++)
            u = fmaf(swgt[i], vel[(size_t)sidx[i] * DD + tid], u);
        u *= (1.f / s_wsum);
        float xd = out[(size_t)q * ZLD + tid];
        pr_ux[tid] = u * xd;
        pr_uu[tid] = u * u;
        pr_xx[tid] = xd * xd;
        float dfe = u - xd;
        pr_l2[tid] = dfe * dfe;
    }
    __syncthreads();
    if (tid == 0) {
        float ux = 0.f, uu = 0.f, xx = 0.f, l2 = 0.f;
        for (int d = 0; d < DD; d++) {
            ux += pr_ux[d]; uu += pr_uu[d]; xx += pr_xx[d]; l2 += pr_l2[d];
        }
        float nu = fmaxf(sqrtf(uu), 1e-8f);
        float nx = fmaxf(sqrtf(xx), 1e-8f);
        out[(size_t)q * ZLD + 64] = 1.f - ux / (nu * nx);
        out[(size_t)q * ZLD + 65] = l2;
    }
}

// ---------------------------------------------------------------------------
extern "C" void kernel_launch(void* const* d_in, const int* in_sizes, int n_in,
                              void* d_out, int out_size)
{
    const float* t    = (const float*)d_in[0];
    const float* z    = (const float*)d_in[1];
    const float* data = (const float*)d_in[2];
    const float* vel  = (const float*)d_in[3];
    const float* W1   = (const float*)d_in[4];
    const float* b1   = (const float*)d_in[5];
    const float* W2   = (const float*)d_in[6];
    const float* b2   = (const float*)d_in[7];
    float* out = (float*)d_out;

    pn2_kernel<<<(PADP + 255) / 256, 256>>>(data);
    mlp_kernel<<<NB / 8, 256>>>(z, t, W1, b1, W2, b2, out);
    knn_pass1<<<dim3(NB / (P1T * QPT), NCH), P1T>>>(z, data);
    knn_pass2<<<NB, 256>>>(vel, out);
}